// round 6
// baseline (speedup 1.0000x reference)
#include <cuda_runtime.h>
#include <cfloat>
#include <math.h>

// ---------------------------------------------------------------------------
// Problem constants
//   B=2, M=256 -> 512 groups, 64 points/group, KNN=16, CIN=64 (3 xyz + 61 feat)
//   MLPS=[64,128], SUMM=192, CALIB=64, EXP=[256,512], OUT=256
// ---------------------------------------------------------------------------

// Scratch (static device arrays; no runtime allocation)
__device__ float d_x_[512 * 64 * 64];      // input panel  [g][c(64)][n(64)]
__device__ int   d_idx_[512 * 64 * 16];    // knn indices  [g][n][k]
__device__ float d_big_[512 * 256 * 64];   // reused: UT1 (128 rows), UT2 (256 rows), exp1 out
__device__ float d_cat_[512 * 192 * 64];   // concat features [g][c(192)][n]
__device__ float d_c_[512 * 64 * 64];      // cal1 out
__device__ float d_gt_[2 * 512 * 256];     // pooled vector, [b][c(512)][m(256)]
__device__ float d_x1_[2 * 256 * 256];     // after red+bn1
__device__ float d_h_[2 * 256 * 256];      // sc1 out
__device__ float d_ws1_[128 * 64];         // stacked edge weights layer1: [W1 ; W2-W1]
__device__ float d_ws2_[256 * 64];         // stacked edge weights layer2

// ---------------------------------------------------------------------------
// f32x2 packed-FMA helpers (2x fp32 throughput; PTX-only on sm_103a)
// ---------------------------------------------------------------------------
__device__ __forceinline__ unsigned long long pack2(float v) {
    unsigned long long r;
    asm("mov.b64 %0, {%1, %1};" : "=l"(r) : "r"(__float_as_uint(v)));
    return r;
}
__device__ __forceinline__ void ffma2(unsigned long long& d,
                                      unsigned long long a, unsigned long long b) {
    asm("fma.rn.f32x2 %0, %1, %2, %0;" : "+l"(d) : "l"(a), "l"(b));
}
__device__ __forceinline__ float lo2(unsigned long long v) { return __uint_as_float((unsigned)v); }
__device__ __forceinline__ float hi2(unsigned long long v) { return __uint_as_float((unsigned)(v >> 32)); }

// ---------------------------------------------------------------------------
// K0: build stacked EdgeConv weights:  rows [0,C) = W1, rows [C,2C) = W2 - W1
// ---------------------------------------------------------------------------
__global__ void prep_kernel(const float* __restrict__ e1w, const float* __restrict__ e2w) {
    int idx = blockIdx.x * blockDim.x + threadIdx.x;
    if (idx < 128 * 64) {
        int r = idx >> 6, c = idx & 63;
        d_ws1_[idx] = (r < 64) ? e1w[r * 128 + c]
                               : e1w[(r - 64) * 128 + 64 + c] - e1w[(r - 64) * 128 + c];
    }
    int i2 = idx - 128 * 64;
    if (i2 >= 0 && i2 < 256 * 64) {
        int r = i2 >> 6, c = i2 & 63;
        d_ws2_[i2] = (r < 128) ? e2w[r * 128 + c]
                               : e2w[(r - 128) * 128 + 64 + c] - e2w[(r - 128) * 128 + c];
    }
}

// ---------------------------------------------------------------------------
// K1: build input panel d_x (xyz+feats transposed) + 16-NN per point.
// One block per group, 64 threads (one per point).
// ---------------------------------------------------------------------------
__global__ void knn_kernel(const float* __restrict__ xyz, const float* __restrict__ feats) {
    int g = blockIdx.x, t = threadIdx.x;
    __shared__ float px[64], py[64], pz[64], xx[64];
    __shared__ float sbuf[64 * 65];   // feat staging (3904) / padded pd rows (64x65)

    int b3 = (g * 64 + t) * 3;
    float ax = xyz[b3 + 0], ay = xyz[b3 + 1], az = xyz[b3 + 2];
    px[t] = ax; py[t] = ay; pz[t] = az;
    xx[t] = ax * ax + ay * ay + az * az;

    float* xg = d_x_ + (size_t)g * 4096;
    xg[0 * 64 + t] = ax; xg[1 * 64 + t] = ay; xg[2 * 64 + t] = az;

    // stage feats (coalesced) then transpose into d_x channels 3..63
    const float* fg = feats + (size_t)g * 64 * 61;
    for (int i = 0; i < 61; i++) sbuf[i * 64 + t] = fg[i * 64 + t];
    __syncthreads();
    for (int c = 0; c < 61; c++) xg[(3 + c) * 64 + t] = sbuf[t * 61 + c];
    __syncthreads();

    // pd row (padded to 65 -> conflict-free)
    float* row = &sbuf[t * 65];
    float xn = xx[t];
    for (int m = 0; m < 64; m++)
        row[m] = 2.0f * (ax * px[m] + ay * py[m] + az * pz[m]) - xn - xx[m];

    // top-16 by selection (only the SET matters; max-over-k is order-invariant)
    int* ig = d_idx_ + (g * 64 + t) * 16;
    for (int k = 0; k < 16; k++) {
        float best = -FLT_MAX; int bi = 0;
        for (int m = 0; m < 64; m++) {
            float v = row[m];
            if (v > best) { best = v; bi = m; }
        }
        ig[k] = bi;
        row[bi] = -FLT_MAX;
    }
}

// ---------------------------------------------------------------------------
// gather-max epilogue of EdgeConv (vectorized, U transposed in smem).
// ut layout per group: rows [0,Cout) = U = W1@X, rows [Cout,2Cout) = T = (W2-W1)@X
// out[o,n] = max_k relu( bn( U[o, idx[n,k]] + T[o,n] ) )
// Thread (og,n) handles o-quads {og*4 + 16*j} for column n; one LDS.128 per (k, o-quad).
// ---------------------------------------------------------------------------
__global__ void __launch_bounds__(256) gather_kernel(const float* __restrict__ ut,
                              const float* __restrict__ gv, const float* __restrict__ bv,
                              int Cout, int chanOff) {
    __shared__ __align__(16) float Ust[64][132];   // [n][o], pad -> float4 @ 4-way max
    __shared__ int sidx[64 * 17];
    int g = blockIdx.x, t = threadIdx.x;
    const float INVS = rsqrtf(1.0f + 1e-5f);

    const float* utg = ut + (size_t)g * (2 * Cout * 64);
    int tot = Cout * 64;
    for (int i = t; i < tot; i += 256) {
        int o = i >> 6, n = i & 63;
        Ust[n][o] = utg[i];
    }
    const int* idg = d_idx_ + g * 1024;
    for (int i = t; i < 1024; i += 256) {
        int n = i >> 4, k = i & 15;
        sidx[n * 17 + k] = idg[i];
    }
    __syncthreads();

    int n = t & 63, og = t >> 6;   // og in 0..3
    int ni[16];
    #pragma unroll
    for (int k = 0; k < 16; k++) ni[k] = sidx[n * 17 + k];

    float* outg = d_cat_ + (size_t)g * 12288 + (size_t)chanOff * 64;
    for (int o4 = og * 4; o4 < Cout; o4 += 16) {
        float T0 = utg[(Cout + o4 + 0) * 64 + n];
        float T1 = utg[(Cout + o4 + 1) * 64 + n];
        float T2 = utg[(Cout + o4 + 2) * 64 + n];
        float T3 = utg[(Cout + o4 + 3) * 64 + n];
        float4 gvv = *reinterpret_cast<const float4*>(&gv[o4]);
        float4 bvv = *reinterpret_cast<const float4*>(&bv[o4]);
        float s0 = gvv.x * INVS, s1 = gvv.y * INVS, s2 = gvv.z * INVS, s3 = gvv.w * INVS;
        float m0 = -FLT_MAX, m1 = -FLT_MAX, m2 = -FLT_MAX, m3 = -FLT_MAX;
        #pragma unroll
        for (int k = 0; k < 16; k++) {
            float4 u = *reinterpret_cast<const float4*>(&Ust[ni[k]][o4]);
            m0 = fmaxf(m0, fmaf(u.x + T0, s0, bvv.x));
            m1 = fmaxf(m1, fmaf(u.y + T1, s1, bvv.y));
            m2 = fmaxf(m2, fmaf(u.z + T2, s2, bvv.z));
            m3 = fmaxf(m3, fmaf(u.w + T3, s3, bvv.w));
        }
        outg[(o4 + 0) * 64 + n] = fmaxf(m0, 0.0f);
        outg[(o4 + 1) * 64 + n] = fmaxf(m1, 0.0f);
        outg[(o4 + 2) * 64 + n] = fmaxf(m2, 0.0f);
        outg[(o4 + 3) * 64 + n] = fmaxf(m3, 0.0f);
    }
}

// ---------------------------------------------------------------------------
// Generic fused GEMM:  out(64o x 64col tile) = epi( W(O x CIN) @ X(CIN x cols) )
// Double-buffered smem pipeline: prefetch next 16-channel chunk into registers
// during compute, single __syncthreads per chunk.
// Epilogues: 0 raw | 1 relu(bn) | 2 sigmoid-gate (cal2) | 3 relu(bn)+max-over-col
//            4 red: relu(bn)*2 ->bn1 | 5 bias+relu | 6 final: bn2(x1 + acc + b)
// ---------------------------------------------------------------------------
template<int EPI>
__global__ void __launch_bounds__(256)
gemm_k(const float* __restrict__ X, int imgStride, int cpi,
       const float* __restrict__ W, int CIN,
       float* out, int outImgStride, int outCpi, int chanOff,
       const float* p0, const float* p1, const float* p2, const float* p3,
       const float* aux) {
    __shared__ __align__(16) float Xs[2][16][64];
    __shared__ __align__(16) unsigned long long Wsp[2][16][66];  // [c][o], packed f32x2

    const int g = blockIdx.x;
    const int colBase = blockIdx.y << 6;
    const int oBase = blockIdx.z << 6;
    const int t = threadIdx.x;
    const int tn = t & 15, to = t >> 4;

    unsigned long long acc2[4][2];
    #pragma unroll
    for (int i = 0; i < 4; i++) { acc2[i][0] = 0ull; acc2[i][1] = 0ull; }

    const float* Xg = X + (size_t)g * imgStride + colBase;
    const float* Wg = W + (size_t)oBase * CIN;

    // staging roles
    const int sx_r = t >> 4, sx_c = (t & 15) << 2;   // X: row 0..15, col4
    const int sw_o = t >> 2, sw_c = t & 3;           // W: o 0..63, 4 c's

    const int nch = CIN >> 4;
    float4 xf, wf;

    // prologue: chunk 0
    xf = *reinterpret_cast<const float4*>(&Xg[(size_t)sx_r * cpi + sx_c]);
    wf = *reinterpret_cast<const float4*>(&Wg[(size_t)sw_o * CIN + (sw_c << 2)]);
    *reinterpret_cast<float4*>(&Xs[0][sx_r][sx_c]) = xf;
    Wsp[0][(sw_c << 2) + 0][sw_o] = pack2(wf.x);
    Wsp[0][(sw_c << 2) + 1][sw_o] = pack2(wf.y);
    Wsp[0][(sw_c << 2) + 2][sw_o] = pack2(wf.z);
    Wsp[0][(sw_c << 2) + 3][sw_o] = pack2(wf.w);
    __syncthreads();

    for (int cb = 0; cb < nch; cb++) {
        const int buf = cb & 1;
        const bool has = (cb + 1 < nch);
        if (has) {
            int c0 = (cb + 1) << 4;
            xf = *reinterpret_cast<const float4*>(&Xg[(size_t)(c0 + sx_r) * cpi + sx_c]);
            wf = *reinterpret_cast<const float4*>(&Wg[(size_t)sw_o * CIN + c0 + (sw_c << 2)]);
        }
        #pragma unroll
        for (int c = 0; c < 16; c++) {
            ulonglong2 xv = *reinterpret_cast<const ulonglong2*>(&Xs[buf][c][tn << 2]);
            ulonglong2 wa = *reinterpret_cast<const ulonglong2*>(&Wsp[buf][c][to << 2]);
            ulonglong2 wb = *reinterpret_cast<const ulonglong2*>(&Wsp[buf][c][(to << 2) + 2]);
            ffma2(acc2[0][0], wa.x, xv.x); ffma2(acc2[0][1], wa.x, xv.y);
            ffma2(acc2[1][0], wa.y, xv.x); ffma2(acc2[1][1], wa.y, xv.y);
            ffma2(acc2[2][0], wb.x, xv.x); ffma2(acc2[2][1], wb.x, xv.y);
            ffma2(acc2[3][0], wb.y, xv.x); ffma2(acc2[3][1], wb.y, xv.y);
        }
        if (has) {
            int nb = buf ^ 1;
            *reinterpret_cast<float4*>(&Xs[nb][sx_r][sx_c]) = xf;
            Wsp[nb][(sw_c << 2) + 0][sw_o] = pack2(wf.x);
            Wsp[nb][(sw_c << 2) + 1][sw_o] = pack2(wf.y);
            Wsp[nb][(sw_c << 2) + 2][sw_o] = pack2(wf.z);
            Wsp[nb][(sw_c << 2) + 3][sw_o] = pack2(wf.w);
        }
        __syncthreads();
    }

    float acc[4][4];
    #pragma unroll
    for (int i = 0; i < 4; i++) {
        acc[i][0] = lo2(acc2[i][0]); acc[i][1] = hi2(acc2[i][0]);
        acc[i][2] = lo2(acc2[i][1]); acc[i][3] = hi2(acc2[i][1]);
    }
    const float INVS = rsqrtf(1.0f + 1e-5f);

    if constexpr (EPI == 3) {
        __shared__ float red[64][17];
        #pragma unroll
        for (int i = 0; i < 4; i++) {
            int o = oBase + (to << 2) + i;
            float s = p0[o] * INVS, b = p1[o];
            float m = -FLT_MAX;
            #pragma unroll
            for (int j = 0; j < 4; j++)
                m = fmaxf(m, fmaxf(fmaf(acc[i][j], s, b), 0.0f));
            red[(to << 2) + i][tn] = m;
        }
        __syncthreads();
        if (t < 64) {
            float m = red[t][0];
            #pragma unroll
            for (int q = 1; q < 16; q++) m = fmaxf(m, red[t][q]);
            int bb = g >> 8, mm = g & 255;   // g = b*256 + m
            out[((size_t)bb * 512 + oBase + t) * 256 + mm] = m;
        }
    } else {
        #pragma unroll
        for (int i = 0; i < 4; i++) {
            int o = oBase + (to << 2) + i;
            size_t ob = (size_t)g * outImgStride + (size_t)(chanOff + o) * outCpi
                      + colBase + (tn << 2);
            if constexpr (EPI == 0) {
                #pragma unroll
                for (int j = 0; j < 4; j++) out[ob + j] = acc[i][j];
            } else if constexpr (EPI == 1) {
                float s = p0[o] * INVS, b = p1[o];
                #pragma unroll
                for (int j = 0; j < 4; j++)
                    out[ob + j] = fmaxf(fmaf(acc[i][j], s, b), 0.0f);
            } else if constexpr (EPI == 2) {
                float bb = p0[o];
                #pragma unroll
                for (int j = 0; j < 4; j++) {
                    float v = acc[i][j] + bb;
                    float sg = 1.0f / (1.0f + expf(-v));
                    out[ob + j] = sg * aux[ob + j];
                }
            } else if constexpr (EPI == 4) {
                float sr = p0[o] * INVS, br = p1[o];
                float s1 = p2[o] * INVS, b1 = p3[o];
                #pragma unroll
                for (int j = 0; j < 4; j++) {
                    float r = fmaxf(fmaf(acc[i][j], sr, br), 0.0f);
                    out[ob + j] = fmaf(2.0f * r, s1, b1);
                }
            } else if constexpr (EPI == 5) {
                float bb = p0[o];
                #pragma unroll
                for (int j = 0; j < 4; j++)
                    out[ob + j] = fmaxf(acc[i][j] + bb, 0.0f);
            } else if constexpr (EPI == 6) {
                float bb = p0[o], s2 = p1[o] * INVS, b2 = p2[o];
                #pragma unroll
                for (int j = 0; j < 4; j++) {
                    float v = acc[i][j] + bb + aux[ob + j];
                    out[ob + j] = fmaf(v, s2, b2);
                }
            }
        }
    }
}

// ---------------------------------------------------------------------------
extern "C" void kernel_launch(void* const* d_in, const int* in_sizes, int n_in,
                              void* d_out, int out_size) {
    const float* xyz       = (const float*)d_in[0];
    const float* feats     = (const float*)d_in[1];
    const float* e1_w      = (const float*)d_in[2];
    const float* e1_g      = (const float*)d_in[3];
    const float* e1_b      = (const float*)d_in[4];
    const float* e2_w      = (const float*)d_in[5];
    const float* e2_g      = (const float*)d_in[6];
    const float* e2_b      = (const float*)d_in[7];
    const float* cal1_w    = (const float*)d_in[8];
    const float* cal1_g    = (const float*)d_in[9];
    const float* cal1_b    = (const float*)d_in[10];
    const float* cal2_w    = (const float*)d_in[11];
    const float* cal2_bias = (const float*)d_in[12];
    const float* exp1_w    = (const float*)d_in[13];
    const float* exp1_g    = (const float*)d_in[14];
    const float* exp1_b    = (const float*)d_in[15];
    const float* exp2_w    = (const float*)d_in[16];
    const float* exp2_g    = (const float*)d_in[17];
    const float* exp2_b    = (const float*)d_in[18];
    const float* red_w     = (const float*)d_in[19];
    const float* red_g     = (const float*)d_in[20];
    const float* red_b     = (const float*)d_in[21];
    const float* sc1_w     = (const float*)d_in[22];
    const float* sc1_b     = (const float*)d_in[23];
    const float* sc2_w     = (const float*)d_in[24];
    const float* sc2_b     = (const float*)d_in[25];
    const float* n1_g      = (const float*)d_in[26];
    const float* n1_b      = (const float*)d_in[27];
    const float* n2_g      = (const float*)d_in[28];
    const float* n2_b      = (const float*)d_in[29];

    float *dx, *dbig, *dcat, *dc, *dgt, *dx1, *dh, *dws1, *dws2;
    cudaGetSymbolAddress((void**)&dx,   d_x_);
    cudaGetSymbolAddress((void**)&dbig, d_big_);
    cudaGetSymbolAddress((void**)&dcat, d_cat_);
    cudaGetSymbolAddress((void**)&dc,   d_c_);
    cudaGetSymbolAddress((void**)&dgt,  d_gt_);
    cudaGetSymbolAddress((void**)&dx1,  d_x1_);
    cudaGetSymbolAddress((void**)&dh,   d_h_);
    cudaGetSymbolAddress((void**)&dws1, d_ws1_);
    cudaGetSymbolAddress((void**)&dws2, d_ws2_);

    // K0: stacked edge weights
    prep_kernel<<<96, 256>>>(e1_w, e2_w);
    // K1: input panel + knn
    knn_kernel<<<512, 64>>>(xyz, feats);

    // EdgeConv1: [U;T] = ws1(128x64) @ x  -> gather-max -> d_cat[0:64)
    gemm_k<0><<<dim3(512, 1, 2), 256>>>(dx, 4096, 64, dws1, 64,
                                        dbig, 8192, 64, 0,
                                        nullptr, nullptr, nullptr, nullptr, nullptr);
    gather_kernel<<<512, 256>>>(dbig, e1_g, e1_b, 64, 0);

    // EdgeConv2: [U;T] = ws2(256x64) @ d_cat[0:64)  -> gather-max -> d_cat[64:192)
    gemm_k<0><<<dim3(512, 1, 4), 256>>>(dcat, 12288, 64, dws2, 64,
                                        dbig, 16384, 64, 0,
                                        nullptr, nullptr, nullptr, nullptr, nullptr);
    gather_kernel<<<512, 256>>>(dbig, e2_g, e2_b, 128, 64);

    // calib: c = relu(bn(cal1@x)); x = sigmoid(cal2@c + bias) * x  (gate in-place)
    gemm_k<1><<<dim3(512, 1, 1), 256>>>(dcat, 12288, 64, cal1_w, 192,
                                        dc, 4096, 64, 0,
                                        cal1_g, cal1_b, nullptr, nullptr, nullptr);
    gemm_k<2><<<dim3(512, 1, 3), 256>>>(dc, 4096, 64, cal2_w, 64,
                                        dcat, 12288, 64, 0,
                                        cal2_bias, nullptr, nullptr, nullptr, dcat);

    // exp1: relu(bn(exp1@x))
    gemm_k<1><<<dim3(512, 1, 4), 256>>>(dcat, 12288, 64, exp1_w, 192,
                                        dbig, 16384, 64, 0,
                                        exp1_g, exp1_b, nullptr, nullptr, nullptr);
    // exp2 + max over 64 points, write transposed pooled [b][512][256]
    gemm_k<3><<<dim3(512, 1, 8), 256>>>(dbig, 16384, 64, exp2_w, 256,
                                        dgt, 0, 0, 0,
                                        exp2_g, exp2_b, nullptr, nullptr, nullptr);

    // red: x1 = bn1( 2 * relu(bn(red@pooled)) )
    gemm_k<4><<<dim3(2, 4, 4), 256>>>(dgt, 131072, 256, red_w, 512,
                                      dx1, 65536, 256, 0,
                                      red_g, red_b, n1_g, n1_b, nullptr);
    // sc1: h = relu(sc1@x1 + b)
    gemm_k<5><<<dim3(2, 4, 4), 256>>>(dx1, 65536, 256, sc1_w, 256,
                                      dh, 65536, 256, 0,
                                      sc1_b, nullptr, nullptr, nullptr, nullptr);
    // sc2 + residual + bn2 -> final output (B, 256, 256)
    gemm_k<6><<<dim3(2, 4, 4), 256>>>(dh, 65536, 256, sc2_w, 256,
                                      (float*)d_out, 65536, 256, 0,
                                      sc2_b, n2_g, n2_b, nullptr, dx1);
}

// round 8
// speedup vs baseline: 1.8706x; 1.8706x over previous
#include <cuda_runtime.h>
#include <cstdint>
#include <cfloat>
#include <math.h>

// ---------------------------------------------------------------------------
// Problem constants
//   B=2, M=256 -> 512 groups, 64 points/group, KNN=16, CIN=64 (3 xyz + 61 feat)
//   MLPS=[64,128], SUMM=192, CALIB=64, EXP=[256,512], OUT=256
// ---------------------------------------------------------------------------

// Scratch (static device arrays; no runtime allocation)
__device__ float d_x_[512 * 64 * 64];      // input panel  [g][c(64)][n(64)]
__device__ int   d_idx_[512 * 64 * 16];    // knn indices  [g][n][k]
__device__ float d_big_[512 * 256 * 64];   // reused: UT1 (128 rows), UT2 (256 rows), exp1 out
__device__ float d_cat_[512 * 192 * 64];   // concat features [g][c(192)][n]
__device__ float d_c_[512 * 64 * 64];      // cal1 out
__device__ float d_gt_[2 * 512 * 256];     // pooled vector, [b][c(512)][m(256)]
__device__ float d_x1_[2 * 256 * 256];     // after red+bn1
__device__ float d_h_[2 * 256 * 256];      // sc1 out

// All weights, transposed to [c][o] and pre-duplicated as f32x2 pairs.
// Regions (u64 index):
//   ws1   @0       64c x 128o  (stacked [W1 ; W2-W1], EdgeConv1)
//   ws2   @8192    64c x 256o  (stacked, EdgeConv2)
//   cal1  @24576  192c x  64o
//   cal2  @36864   64c x 192o
//   exp1  @49152  192c x 256o
//   exp2  @98304  256c x 512o
//   red   @229376 512c x 256o
//   sc1   @360448 256c x 256o
//   sc2   @425984 256c x 256o
#define WP_WS1  0
#define WP_WS2  8192
#define WP_CAL1 24576
#define WP_CAL2 36864
#define WP_EXP1 49152
#define WP_EXP2 98304
#define WP_RED  229376
#define WP_SC1  360448
#define WP_SC2  425984
#define WP_TOT  491520
__device__ unsigned long long d_wp_[WP_TOT];

// ---------------------------------------------------------------------------
// f32x2 packed-FMA + cp.async helpers
// ---------------------------------------------------------------------------
__device__ __forceinline__ unsigned long long pack2(float v) {
    unsigned long long r;
    asm("mov.b64 %0, {%1, %1};" : "=l"(r) : "r"(__float_as_uint(v)));
    return r;
}
__device__ __forceinline__ void ffma2(unsigned long long& d,
                                      unsigned long long a, unsigned long long b) {
    asm("fma.rn.f32x2 %0, %1, %2, %0;" : "+l"(d) : "l"(a), "l"(b));
}
__device__ __forceinline__ float lo2(unsigned long long v) { return __uint_as_float((unsigned)v); }
__device__ __forceinline__ float hi2(unsigned long long v) { return __uint_as_float((unsigned)(v >> 32)); }

__device__ __forceinline__ void cp16(unsigned int dst, const void* src) {
    asm volatile("cp.async.cg.shared.global [%0], [%1], 16;" :: "r"(dst), "l"(src));
}
__device__ __forceinline__ void cp_commit() { asm volatile("cp.async.commit_group;"); }
template<int N> __device__ __forceinline__ void cp_wait() {
    asm volatile("cp.async.wait_group %0;" :: "n"(N));
}

// ---------------------------------------------------------------------------
// K0 (x2 launches): transpose + f32x2-pack ALL weights into d_wp_.
// part 0 handles u64 idx [0, WP_EXP2), part 1 handles [WP_EXP2, WP_TOT).
// ---------------------------------------------------------------------------
__global__ void prep_pack(const float* __restrict__ e1w, const float* __restrict__ e2w,
                          const float* __restrict__ cal1w, const float* __restrict__ cal2w,
                          const float* __restrict__ exp1w, const float* __restrict__ exp2w,
                          const float* __restrict__ redw, const float* __restrict__ sc1w,
                          const float* __restrict__ sc2w, int part) {
    int i = blockIdx.x * blockDim.x + threadIdx.x + (part ? WP_EXP2 : 0);
    if (part == 0) {
        if (i >= WP_EXP2) return;
    } else {
        if (i >= WP_TOT) return;
    }
    float v;
    if (i < WP_WS2) {                 // ws1: O=128, C=64
        int l = i - WP_WS1, c = l >> 7, o = l & 127;
        v = (o < 64) ? e1w[o * 128 + c]
                     : e1w[(o - 64) * 128 + 64 + c] - e1w[(o - 64) * 128 + c];
    } else if (i < WP_CAL1) {         // ws2: O=256, C=64
        int l = i - WP_WS2, c = l >> 8, o = l & 255;
        v = (o < 128) ? e2w[o * 128 + c]
                      : e2w[(o - 128) * 128 + 64 + c] - e2w[(o - 128) * 128 + c];
    } else if (i < WP_CAL2) {         // cal1: O=64, C=192
        int l = i - WP_CAL1, c = l >> 6, o = l & 63;
        v = cal1w[o * 192 + c];
    } else if (i < WP_EXP1) {         // cal2: O=192, C=64
        int l = i - WP_CAL2, c = l / 192, o = l % 192;
        v = cal2w[o * 64 + c];
    } else if (i < WP_EXP2) {         // exp1: O=256, C=192
        int l = i - WP_EXP1, c = l >> 8, o = l & 255;
        v = exp1w[o * 192 + c];
    } else if (i < WP_RED) {          // exp2: O=512, C=256
        int l = i - WP_EXP2, c = l >> 9, o = l & 511;
        v = exp2w[o * 256 + c];
    } else if (i < WP_SC1) {          // red: O=256, C=512
        int l = i - WP_RED, c = l >> 8, o = l & 255;
        v = redw[o * 512 + c];
    } else if (i < WP_SC2) {          // sc1: O=256, C=256
        int l = i - WP_SC1, c = l >> 8, o = l & 255;
        v = sc1w[o * 256 + c];
    } else {                          // sc2: O=256, C=256
        int l = i - WP_SC2, c = l >> 8, o = l & 255;
        v = sc2w[o * 256 + c];
    }
    d_wp_[i] = pack2(v);
}

// ---------------------------------------------------------------------------
// K1: build input panel d_x (xyz+feats transposed) + 16-NN per point.
// One block per group, 64 threads (one per point).
// ---------------------------------------------------------------------------
__global__ void knn_kernel(const float* __restrict__ xyz, const float* __restrict__ feats) {
    int g = blockIdx.x, t = threadIdx.x;
    __shared__ float px[64], py[64], pz[64], xx[64];
    __shared__ float sbuf[64 * 65];   // feat staging (3904) / padded pd rows (64x65)

    int b3 = (g * 64 + t) * 3;
    float ax = xyz[b3 + 0], ay = xyz[b3 + 1], az = xyz[b3 + 2];
    px[t] = ax; py[t] = ay; pz[t] = az;
    xx[t] = ax * ax + ay * ay + az * az;

    float* xg = d_x_ + (size_t)g * 4096;
    xg[0 * 64 + t] = ax; xg[1 * 64 + t] = ay; xg[2 * 64 + t] = az;

    // stage feats (coalesced) then transpose into d_x channels 3..63
    const float* fg = feats + (size_t)g * 64 * 61;
    for (int i = 0; i < 61; i++) sbuf[i * 64 + t] = fg[i * 64 + t];
    __syncthreads();
    for (int c = 0; c < 61; c++) xg[(3 + c) * 64 + t] = sbuf[t * 61 + c];
    __syncthreads();

    // pd row (padded to 65 -> conflict-free)
    float* row = &sbuf[t * 65];
    float xn = xx[t];
    for (int m = 0; m < 64; m++)
        row[m] = 2.0f * (ax * px[m] + ay * py[m] + az * pz[m]) - xn - xx[m];

    // top-16 by selection (only the SET matters; max-over-k is order-invariant)
    int* ig = d_idx_ + (g * 64 + t) * 16;
    for (int k = 0; k < 16; k++) {
        float best = -FLT_MAX; int bi = 0;
        for (int m = 0; m < 64; m++) {
            float v = row[m];
            if (v > best) { best = v; bi = m; }
        }
        ig[k] = bi;
        row[bi] = -FLT_MAX;
    }
}

// ---------------------------------------------------------------------------
// gather-max epilogue of EdgeConv (R4 version — 20us, 40 regs, known good).
// ut layout per group: rows [0,Cout) = U = W1@X, rows [Cout,2Cout) = T = (W2-W1)@X
// out[o,n] = max_k relu( bn( U[o, idx[n,k]] + T[o,n] ) )
// ---------------------------------------------------------------------------
__global__ void gather_kernel(const float* __restrict__ ut,
                              const float* __restrict__ gv, const float* __restrict__ bv,
                              int Cout, int chanOff) {
    int g = blockIdx.x, t = threadIdx.x;   // 256 threads
    __shared__ float Us[128 * 64];
    __shared__ int   sidx[64 * 17];
    const float INVS = rsqrtf(1.0f + 1e-5f);

    const float* utg = ut + (size_t)g * (2 * Cout * 64);
    int tot = Cout * 64;
    for (int i = t; i < tot; i += 256) Us[i] = utg[i];
    const int* idg = d_idx_ + g * 1024;
    for (int i = t; i < 1024; i += 256) {
        int n = i >> 4, k = i & 15;
        sidx[n * 17 + k] = idg[i];
    }
    __syncthreads();

    float* outg = d_cat_ + (size_t)g * 12288 + (size_t)chanOff * 64;
    for (int item = t; item < tot; item += 256) {
        int o = item >> 6, n = item & 63;
        float T = utg[(Cout + o) * 64 + n];
        float s = gv[o] * INVS, b = bv[o];
        const float* Uo = &Us[o * 64];
        const int*   ni = &sidx[n * 17];
        float m = -FLT_MAX;
        #pragma unroll
        for (int k = 0; k < 16; k++) {
            float v = fmaf(Uo[ni[k]] + T, s, b);
            m = fmaxf(m, fmaxf(v, 0.0f));
        }
        outg[o * 64 + n] = m;
    }
}

// ---------------------------------------------------------------------------
// Generic fused GEMM:  out(64o x 64col tile) = epi( W(wO x CIN) @ X(CIN x cols) )
// W comes pre-transposed+f32x2-packed: Wp[c * wO + o] = {w,w}.
// 3-stage cp.async pipeline (LDGSTS -> smem, zero register residency),
// one __syncthreads + one wait_group per 16-channel chunk.
// Epilogues: 0 raw | 1 relu(bn) | 2 sigmoid-gate (cal2) | 3 relu(bn)+max-over-col
//            4 red: relu(bn)*2 ->bn1 | 5 bias+relu | 6 final: bn2(x1 + acc + b)
// ---------------------------------------------------------------------------
template<int EPI>
__global__ void __launch_bounds__(256)
gemm_k(const float* __restrict__ X, int imgStride, int cpi,
       const unsigned long long* __restrict__ Wp, int CIN, int wO,
       float* out, int outImgStride, int outCpi, int chanOff,
       const float* p0, const float* p1, const float* p2, const float* p3,
       const float* aux) {
    __shared__ __align__(16) float Xs[3][16][64];                  // 12 KB
    __shared__ __align__(16) unsigned long long Ws[3][16][64];     // 24 KB

    const int g = blockIdx.x;
    const int colBase = blockIdx.y << 6;
    const int oBase = blockIdx.z << 6;
    const int t = threadIdx.x;
    const int tn = t & 15, to = t >> 4;

    const float* Xg = X + (size_t)g * imgStride + colBase;
    const unsigned long long* Wg = Wp + oBase;

    // copy roles: row = t>>4 (16 rows per chunk)
    const int cr = t >> 4;
    const int xc = (t & 15) << 2;      // X: 16B per thread per chunk
    const int wu = (t & 15) << 1;      // W: 2x16B per thread per chunk (u64 idx wu, wu+32)

    const unsigned int xs_s = (unsigned int)__cvta_generic_to_shared(&Xs[0][0][0]);
    const unsigned int ws_s = (unsigned int)__cvta_generic_to_shared(&Ws[0][0][0]);
    const int nch = CIN >> 4;

    unsigned long long acc2[4][2];
    #pragma unroll
    for (int i = 0; i < 4; i++) { acc2[i][0] = 0ull; acc2[i][1] = 0ull; }

    auto prefetch = [&](int cb, int st) {
        if (cb < nch) {
            const int c0 = cb << 4;
            cp16(xs_s + (unsigned int)(st * 1024 + cr * 64 + xc) * 4,
                 Xg + (size_t)(c0 + cr) * cpi + xc);
            const unsigned long long* wrow = Wg + (size_t)(c0 + cr) * wO;
            cp16(ws_s + (unsigned int)(st * 1024 + cr * 64 + wu) * 8, wrow + wu);
            cp16(ws_s + (unsigned int)(st * 1024 + cr * 64 + wu + 32) * 8, wrow + wu + 32);
        }
        cp_commit();
    };

    prefetch(0, 0);
    prefetch(1, 1);

    int st = 0, stn = 2;   // current stage, stage for (cb+2)
    for (int cb = 0; cb < nch; cb++) {
        cp_wait<1>();          // chunk cb resident
        __syncthreads();       // visible to all; stage stn's old readers are done
        prefetch(cb + 2, stn);
        #pragma unroll
        for (int c = 0; c < 16; c++) {
            ulonglong2 xv = *reinterpret_cast<const ulonglong2*>(&Xs[st][c][tn << 2]);
            ulonglong2 wa = *reinterpret_cast<const ulonglong2*>(&Ws[st][c][to << 2]);
            ulonglong2 wb = *reinterpret_cast<const ulonglong2*>(&Ws[st][c][(to << 2) + 2]);
            ffma2(acc2[0][0], wa.x, xv.x); ffma2(acc2[0][1], wa.x, xv.y);
            ffma2(acc2[1][0], wa.y, xv.x); ffma2(acc2[1][1], wa.y, xv.y);
            ffma2(acc2[2][0], wb.x, xv.x); ffma2(acc2[2][1], wb.x, xv.y);
            ffma2(acc2[3][0], wb.y, xv.x); ffma2(acc2[3][1], wb.y, xv.y);
        }
        st = (st == 2) ? 0 : st + 1;
        stn = (stn == 2) ? 0 : stn + 1;
    }

    float acc[4][4];
    #pragma unroll
    for (int i = 0; i < 4; i++) {
        acc[i][0] = lo2(acc2[i][0]); acc[i][1] = hi2(acc2[i][0]);
        acc[i][2] = lo2(acc2[i][1]); acc[i][3] = hi2(acc2[i][1]);
    }
    const float INVS = rsqrtf(1.0f + 1e-5f);

    if constexpr (EPI == 3) {
        __shared__ float red[64][17];
        #pragma unroll
        for (int i = 0; i < 4; i++) {
            int o = oBase + (to << 2) + i;
            float s = p0[o] * INVS, b = p1[o];
            float m = -FLT_MAX;
            #pragma unroll
            for (int j = 0; j < 4; j++)
                m = fmaxf(m, fmaxf(fmaf(acc[i][j], s, b), 0.0f));
            red[(to << 2) + i][tn] = m;
        }
        __syncthreads();
        if (t < 64) {
            float m = red[t][0];
            #pragma unroll
            for (int q = 1; q < 16; q++) m = fmaxf(m, red[t][q]);
            int bb = g >> 8, mm = g & 255;   // g = b*256 + m
            out[((size_t)bb * 512 + oBase + t) * 256 + mm] = m;
        }
    } else {
        #pragma unroll
        for (int i = 0; i < 4; i++) {
            int o = oBase + (to << 2) + i;
            size_t ob = (size_t)g * outImgStride + (size_t)(chanOff + o) * outCpi
                      + colBase + (tn << 2);
            if constexpr (EPI == 0) {
                #pragma unroll
                for (int j = 0; j < 4; j++) out[ob + j] = acc[i][j];
            } else if constexpr (EPI == 1) {
                float s = p0[o] * INVS, b = p1[o];
                #pragma unroll
                for (int j = 0; j < 4; j++)
                    out[ob + j] = fmaxf(fmaf(acc[i][j], s, b), 0.0f);
            } else if constexpr (EPI == 2) {
                float bb = p0[o];
                #pragma unroll
                for (int j = 0; j < 4; j++) {
                    float v = acc[i][j] + bb;
                    float sg = 1.0f / (1.0f + expf(-v));
                    out[ob + j] = sg * aux[ob + j];
                }
            } else if constexpr (EPI == 4) {
                float sr = p0[o] * INVS, br = p1[o];
                float s1 = p2[o] * INVS, b1 = p3[o];
                #pragma unroll
                for (int j = 0; j < 4; j++) {
                    float r = fmaxf(fmaf(acc[i][j], sr, br), 0.0f);
                    out[ob + j] = fmaf(2.0f * r, s1, b1);
                }
            } else if constexpr (EPI == 5) {
                float bb = p0[o];
                #pragma unroll
                for (int j = 0; j < 4; j++)
                    out[ob + j] = fmaxf(acc[i][j] + bb, 0.0f);
            } else if constexpr (EPI == 6) {
                float bb = p0[o], s2 = p1[o] * INVS, b2 = p2[o];
                #pragma unroll
                for (int j = 0; j < 4; j++) {
                    float v = acc[i][j] + bb + aux[ob + j];
                    out[ob + j] = fmaf(v, s2, b2);
                }
            }
        }
    }
}

// ---------------------------------------------------------------------------
extern "C" void kernel_launch(void* const* d_in, const int* in_sizes, int n_in,
                              void* d_out, int out_size) {
    const float* xyz       = (const float*)d_in[0];
    const float* feats     = (const float*)d_in[1];
    const float* e1_w      = (const float*)d_in[2];
    const float* e1_g      = (const float*)d_in[3];
    const float* e1_b      = (const float*)d_in[4];
    const float* e2_w      = (const float*)d_in[5];
    const float* e2_g      = (const float*)d_in[6];
    const float* e2_b      = (const float*)d_in[7];
    const float* cal1_w    = (const float*)d_in[8];
    const float* cal1_g    = (const float*)d_in[9];
    const float* cal1_b    = (const float*)d_in[10];
    const float* cal2_w    = (const float*)d_in[11];
    const float* cal2_bias = (const float*)d_in[12];
    const float* exp1_w    = (const float*)d_in[13];
    const float* exp1_g    = (const float*)d_in[14];
    const float* exp1_b    = (const float*)d_in[15];
    const float* exp2_w    = (const float*)d_in[16];
    const float* exp2_g    = (const float*)d_in[17];
    const float* exp2_b    = (const float*)d_in[18];
    const float* red_w     = (const float*)d_in[19];
    const float* red_g     = (const float*)d_in[20];
    const float* red_b     = (const float*)d_in[21];
    const float* sc1_w     = (const float*)d_in[22];
    const float* sc1_b     = (const float*)d_in[23];
    const float* sc2_w     = (const float*)d_in[24];
    const float* sc2_b     = (const float*)d_in[25];
    const float* n1_g      = (const float*)d_in[26];
    const float* n1_b      = (const float*)d_in[27];
    const float* n2_g      = (const float*)d_in[28];
    const float* n2_b      = (const float*)d_in[29];

    float *dx, *dbig, *dcat, *dc, *dgt, *dx1, *dh;
    unsigned long long* dwp;
    cudaGetSymbolAddress((void**)&dx,   d_x_);
    cudaGetSymbolAddress((void**)&dbig, d_big_);
    cudaGetSymbolAddress((void**)&dcat, d_cat_);
    cudaGetSymbolAddress((void**)&dc,   d_c_);
    cudaGetSymbolAddress((void**)&dgt,  d_gt_);
    cudaGetSymbolAddress((void**)&dx1,  d_x1_);
    cudaGetSymbolAddress((void**)&dh,   d_h_);
    cudaGetSymbolAddress((void**)&dwp,  d_wp_);

    // K0 a/b: pack all weights (split in two so ncu's launch #5 is a GEMM)
    prep_pack<<<(WP_EXP2 + 255) / 256, 256>>>(e1_w, e2_w, cal1_w, cal2_w, exp1_w,
                                              exp2_w, red_w, sc1_w, sc2_w, 0);
    prep_pack<<<(WP_TOT - WP_EXP2 + 255) / 256, 256>>>(e1_w, e2_w, cal1_w, cal2_w, exp1_w,
                                                       exp2_w, red_w, sc1_w, sc2_w, 1);
    // K1: input panel + knn
    knn_kernel<<<512, 64>>>(xyz, feats);

    // EdgeConv1: [U;T] = ws1(128x64) @ x  -> gather-max -> d_cat[0:64)
    gemm_k<0><<<dim3(512, 1, 2), 256>>>(dx, 4096, 64, dwp + WP_WS1, 64, 128,
                                        dbig, 8192, 64, 0,
                                        nullptr, nullptr, nullptr, nullptr, nullptr);
    gather_kernel<<<512, 256>>>(dbig, e1_g, e1_b, 64, 0);

    // EdgeConv2 (this is ncu launch #5): [U;T] = ws2(256x64) @ d_cat[0:64)
    gemm_k<0><<<dim3(512, 1, 4), 256>>>(dcat, 12288, 64, dwp + WP_WS2, 64, 256,
                                        dbig, 16384, 64, 0,
                                        nullptr, nullptr, nullptr, nullptr, nullptr);
    gather_kernel<<<512, 256>>>(dbig, e2_g, e2_b, 128, 64);

    // calib: c = relu(bn(cal1@x)); x = sigmoid(cal2@c + bias) * x  (gate in-place)
    gemm_k<1><<<dim3(512, 1, 1), 256>>>(dcat, 12288, 64, dwp + WP_CAL1, 192, 64,
                                        dc, 4096, 64, 0,
                                        cal1_g, cal1_b, nullptr, nullptr, nullptr);
    gemm_k<2><<<dim3(512, 1, 3), 256>>>(dc, 4096, 64, dwp + WP_CAL2, 64, 192,
                                        dcat, 12288, 64, 0,
                                        cal2_bias, nullptr, nullptr, nullptr, dcat);

    // exp1: relu(bn(exp1@x))
    gemm_k<1><<<dim3(512, 1, 4), 256>>>(dcat, 12288, 64, dwp + WP_EXP1, 192, 256,
                                        dbig, 16384, 64, 0,
                                        exp1_g, exp1_b, nullptr, nullptr, nullptr);
    // exp2 + max over 64 points, write transposed pooled [b][512][256]
    gemm_k<3><<<dim3(512, 1, 8), 256>>>(dbig, 16384, 64, dwp + WP_EXP2, 256, 512,
                                        dgt, 0, 0, 0,
                                        exp2_g, exp2_b, nullptr, nullptr, nullptr);

    // red: x1 = bn1( 2 * relu(bn(red@pooled)) )
    gemm_k<4><<<dim3(2, 4, 4), 256>>>(dgt, 131072, 256, dwp + WP_RED, 512, 256,
                                      dx1, 65536, 256, 0,
                                      red_g, red_b, n1_g, n1_b, nullptr);
    // sc1: h = relu(sc1@x1 + b)
    gemm_k<5><<<dim3(2, 4, 4), 256>>>(dx1, 65536, 256, dwp + WP_SC1, 256, 256,
                                      dh, 65536, 256, 0,
                                      sc1_b, nullptr, nullptr, nullptr, nullptr);
    // sc2 + residual + bn2 -> final output (B, 256, 256)
    gemm_k<6><<<dim3(2, 4, 4), 256>>>(dh, 65536, 256, dwp + WP_SC2, 256, 256,
                                      (float*)d_out, 65536, 256, 0,
                                      sc2_b, n2_g, n2_b, nullptr, dx1);
}

// round 9
// speedup vs baseline: 2.4696x; 1.3202x over previous
#include <cuda_runtime.h>
#include <cstdint>
#include <cfloat>
#include <math.h>

// ---------------------------------------------------------------------------
// Problem constants
//   B=2, M=256 -> 512 groups, 64 points/group, KNN=16, CIN=64 (3 xyz + 61 feat)
//   MLPS=[64,128], SUMM=192, CALIB=64, EXP=[256,512], OUT=256
// ---------------------------------------------------------------------------

// Scratch (static device arrays; no runtime allocation)
__device__ float d_x_[512 * 64 * 64];      // input panel  [g][c(64)][n(64)]
__device__ int   d_idx_[512 * 64 * 16];    // knn indices  [g][n][k]
__device__ float d_big_[512 * 256 * 64];   // reused: UT1 (128 rows), UT2 (256 rows), exp1 out
__device__ float d_cat_[512 * 192 * 64];   // concat features [g][c(192)][n]
__device__ float d_c_[512 * 64 * 64];      // cal1 out
__device__ float d_gt_[2 * 512 * 256];     // pooled vector, [b][c(512)][m(256)]
__device__ float d_x1_[2 * 256 * 256];     // after red+bn1
__device__ float d_h_[2 * 256 * 256];      // sc1 out

// All weights, transposed to [c][o] (plain float — o-pairs are natural f32x2).
// Regions (float index):
//   ws1   @0       64c x 128o  (stacked [W1 ; W2-W1], EdgeConv1)
//   ws2   @8192    64c x 256o  (stacked, EdgeConv2)
//   cal1  @24576  192c x  64o
//   cal2  @36864   64c x 192o
//   exp1  @49152  192c x 256o
//   exp2  @98304  256c x 512o
//   red   @229376 512c x 256o
//   sc1   @360448 256c x 256o
//   sc2   @425984 256c x 256o
#define WP_WS1  0
#define WP_WS2  8192
#define WP_CAL1 24576
#define WP_CAL2 36864
#define WP_EXP1 49152
#define WP_EXP2 98304
#define WP_RED  229376
#define WP_SC1  360448
#define WP_SC2  425984
#define WP_TOT  491520
__device__ float d_wt_[WP_TOT];

// ---------------------------------------------------------------------------
// f32x2 packed-FMA + cp.async helpers
// ---------------------------------------------------------------------------
__device__ __forceinline__ unsigned long long pack2(float v) {
    unsigned long long r;
    asm("mov.b64 %0, {%1, %1};" : "=l"(r) : "r"(__float_as_uint(v)));
    return r;
}
__device__ __forceinline__ void ffma2(unsigned long long& d,
                                      unsigned long long a, unsigned long long b) {
    asm("fma.rn.f32x2 %0, %1, %2, %0;" : "+l"(d) : "l"(a), "l"(b));
}
__device__ __forceinline__ float lo2(unsigned long long v) { return __uint_as_float((unsigned)v); }
__device__ __forceinline__ float hi2(unsigned long long v) { return __uint_as_float((unsigned)(v >> 32)); }

__device__ __forceinline__ void cp16(unsigned int dst, const void* src) {
    asm volatile("cp.async.cg.shared.global [%0], [%1], 16;" :: "r"(dst), "l"(src));
}
__device__ __forceinline__ void cp_commit() { asm volatile("cp.async.commit_group;"); }
template<int N> __device__ __forceinline__ void cp_wait() {
    asm volatile("cp.async.wait_group %0;" :: "n"(N));
}

// ---------------------------------------------------------------------------
// K0 (x2 launches): transpose ALL weights into d_wt_ ([c][o], plain float).
// ---------------------------------------------------------------------------
__global__ void prep_pack(const float* __restrict__ e1w, const float* __restrict__ e2w,
                          const float* __restrict__ cal1w, const float* __restrict__ cal2w,
                          const float* __restrict__ exp1w, const float* __restrict__ exp2w,
                          const float* __restrict__ redw, const float* __restrict__ sc1w,
                          const float* __restrict__ sc2w, int part) {
    int i = blockIdx.x * blockDim.x + threadIdx.x + (part ? WP_EXP2 : 0);
    if (part == 0) {
        if (i >= WP_EXP2) return;
    } else {
        if (i >= WP_TOT) return;
    }
    float v;
    if (i < WP_WS2) {                 // ws1: O=128, C=64
        int l = i - WP_WS1, c = l >> 7, o = l & 127;
        v = (o < 64) ? e1w[o * 128 + c]
                     : e1w[(o - 64) * 128 + 64 + c] - e1w[(o - 64) * 128 + c];
    } else if (i < WP_CAL1) {         // ws2: O=256, C=64
        int l = i - WP_WS2, c = l >> 8, o = l & 255;
        v = (o < 128) ? e2w[o * 128 + c]
                      : e2w[(o - 128) * 128 + 64 + c] - e2w[(o - 128) * 128 + c];
    } else if (i < WP_CAL2) {         // cal1: O=64, C=192
        int l = i - WP_CAL1, c = l >> 6, o = l & 63;
        v = cal1w[o * 192 + c];
    } else if (i < WP_EXP1) {         // cal2: O=192, C=64
        int l = i - WP_CAL2, c = l / 192, o = l % 192;
        v = cal2w[o * 64 + c];
    } else if (i < WP_EXP2) {         // exp1: O=256, C=192
        int l = i - WP_EXP1, c = l >> 8, o = l & 255;
        v = exp1w[o * 192 + c];
    } else if (i < WP_RED) {          // exp2: O=512, C=256
        int l = i - WP_EXP2, c = l >> 9, o = l & 511;
        v = exp2w[o * 256 + c];
    } else if (i < WP_SC1) {          // red: O=256, C=512
        int l = i - WP_RED, c = l >> 8, o = l & 255;
        v = redw[o * 512 + c];
    } else if (i < WP_SC2) {          // sc1: O=256, C=256
        int l = i - WP_SC1, c = l >> 8, o = l & 255;
        v = sc1w[o * 256 + c];
    } else {                          // sc2: O=256, C=256
        int l = i - WP_SC2, c = l >> 8, o = l & 255;
        v = sc2w[o * 256 + c];
    }
    d_wt_[i] = v;
}

// ---------------------------------------------------------------------------
// K1: build input panel d_x (xyz+feats transposed) + 16-NN per point.
// ---------------------------------------------------------------------------
__global__ void knn_kernel(const float* __restrict__ xyz, const float* __restrict__ feats) {
    int g = blockIdx.x, t = threadIdx.x;
    __shared__ float px[64], py[64], pz[64], xx[64];
    __shared__ float sbuf[64 * 65];   // feat staging (3904) / padded pd rows (64x65)

    int b3 = (g * 64 + t) * 3;
    float ax = xyz[b3 + 0], ay = xyz[b3 + 1], az = xyz[b3 + 2];
    px[t] = ax; py[t] = ay; pz[t] = az;
    xx[t] = ax * ax + ay * ay + az * az;

    float* xg = d_x_ + (size_t)g * 4096;
    xg[0 * 64 + t] = ax; xg[1 * 64 + t] = ay; xg[2 * 64 + t] = az;

    // stage feats (coalesced) then transpose into d_x channels 3..63
    const float* fg = feats + (size_t)g * 64 * 61;
    for (int i = 0; i < 61; i++) sbuf[i * 64 + t] = fg[i * 64 + t];
    __syncthreads();
    for (int c = 0; c < 61; c++) xg[(3 + c) * 64 + t] = sbuf[t * 61 + c];
    __syncthreads();

    // pd row (padded to 65 -> conflict-free)
    float* row = &sbuf[t * 65];
    float xn = xx[t];
    for (int m = 0; m < 64; m++)
        row[m] = 2.0f * (ax * px[m] + ay * py[m] + az * pz[m]) - xn - xx[m];

    // top-16 by selection (only the SET matters; max-over-k is order-invariant)
    int* ig = d_idx_ + (g * 64 + t) * 16;
    for (int k = 0; k < 16; k++) {
        float best = -FLT_MAX; int bi = 0;
        for (int m = 0; m < 64; m++) {
            float v = row[m];
            if (v > best) { best = v; bi = m; }
        }
        ig[k] = bi;
        row[bi] = -FLT_MAX;
    }
}

// ---------------------------------------------------------------------------
// gather-max epilogue of EdgeConv (R4 version — known good).
// ---------------------------------------------------------------------------
__global__ void gather_kernel(const float* __restrict__ ut,
                              const float* __restrict__ gv, const float* __restrict__ bv,
                              int Cout, int chanOff) {
    int g = blockIdx.x, t = threadIdx.x;   // 256 threads
    __shared__ float Us[128 * 64];
    __shared__ int   sidx[64 * 17];
    const float INVS = rsqrtf(1.0f + 1e-5f);

    const float* utg = ut + (size_t)g * (2 * Cout * 64);
    int tot = Cout * 64;
    for (int i = t; i < tot; i += 256) Us[i] = utg[i];
    const int* idg = d_idx_ + g * 1024;
    for (int i = t; i < 1024; i += 256) {
        int n = i >> 4, k = i & 15;
        sidx[n * 17 + k] = idg[i];
    }
    __syncthreads();

    float* outg = d_cat_ + (size_t)g * 12288 + (size_t)chanOff * 64;
    for (int item = t; item < tot; item += 256) {
        int o = item >> 6, n = item & 63;
        float T = utg[(Cout + o) * 64 + n];
        float s = gv[o] * INVS, b = bv[o];
        const float* Uo = &Us[o * 64];
        const int*   ni = &sidx[n * 17];
        float m = -FLT_MAX;
        #pragma unroll
        for (int k = 0; k < 16; k++) {
            float v = fmaf(Uo[ni[k]] + T, s, b);
            m = fmaxf(m, fmaxf(v, 0.0f));
        }
        outg[o * 64 + n] = m;
    }
}

// ---------------------------------------------------------------------------
// Fused GEMM, o-paired FFMA2:  out(OT o x 64col) = epi( W @ X )
// W pre-transposed [c][wO] plain float: consecutive o's ARE the f32x2 pair.
// Per thread: OPT=OT/16 output rows (OPT/2 pairs) x 4 cols.
// Per c-step: 1 LDS.128 X + OPT/4 LDS.128 W + 16 FFMA2 (OT=128).
// 3-stage cp.async pipeline, one sync per 16-channel chunk.
// ---------------------------------------------------------------------------
template<int EPI, int OT>
__global__ void __launch_bounds__(256)
gemm_k(const float* __restrict__ X, int imgStride, int cpi,
       const float* __restrict__ Wt, int CIN, int wO,
       float* out, int outImgStride, int outCpi, int chanOff,
       const float* p0, const float* p1, const float* p2, const float* p3,
       const float* aux) {
    constexpr int OPT = OT / 16;       // outputs per thread (8 or 4)
    constexpr int PAIRS = OPT / 2;     // f32x2 pairs per thread (4 or 2)
    __shared__ __align__(16) float Xs[3][16][64];
    __shared__ __align__(16) float Ws[3][16][OT];

    const int g = blockIdx.x;
    const int colBase = blockIdx.y << 6;
    const int oBase = blockIdx.z * OT;
    const int t = threadIdx.x;
    const int tn = t & 15, to = t >> 4;

    const float* Xg = X + (size_t)g * imgStride + colBase;

    // staging roles
    const int cr = t >> 4;             // chunk row 0..15
    const int xc = (t & 15) << 2;      // X col (float)
    const unsigned int xs_s = (unsigned int)__cvta_generic_to_shared(&Xs[0][0][0]);
    const unsigned int ws_s = (unsigned int)__cvta_generic_to_shared(&Ws[0][0][0]);
    const int nch = CIN >> 4;

    unsigned long long acc2[PAIRS][4];
    #pragma unroll
    for (int p = 0; p < PAIRS; p++)
        #pragma unroll
        for (int j = 0; j < 4; j++) acc2[p][j] = 0ull;

    auto prefetch = [&](int cb, int st) {
        if (cb < nch) {
            const int c0 = cb << 4;
            cp16(xs_s + (unsigned int)(st * 1024 + cr * 64 + xc) * 4,
                 Xg + (size_t)(c0 + cr) * cpi + xc);
            const float* wrow = Wt + (size_t)(c0 + cr) * wO + oBase;
            if constexpr (OT == 128) {
                const int wc = (t & 15) << 3;
                cp16(ws_s + (unsigned int)(st * 16 * OT + cr * OT + wc) * 4, wrow + wc);
                cp16(ws_s + (unsigned int)(st * 16 * OT + cr * OT + wc + 4) * 4, wrow + wc + 4);
            } else {
                const int wc = (t & 15) << 2;
                cp16(ws_s + (unsigned int)(st * 16 * OT + cr * OT + wc) * 4, wrow + wc);
            }
        }
        cp_commit();
    };

    prefetch(0, 0);
    prefetch(1, 1);

    int st = 0, stn = 2;
    for (int cb = 0; cb < nch; cb++) {
        cp_wait<1>();
        __syncthreads();
        prefetch(cb + 2, stn);
        #pragma unroll
        for (int c = 0; c < 16; c++) {
            float4 xv = *reinterpret_cast<const float4*>(&Xs[st][c][tn << 2]);
            unsigned long long xd0 = pack2(xv.x), xd1 = pack2(xv.y);
            unsigned long long xd2 = pack2(xv.z), xd3 = pack2(xv.w);
            const ulonglong2* wr = reinterpret_cast<const ulonglong2*>(&Ws[st][c][to * OPT]);
            unsigned long long wp[PAIRS];
            {
                ulonglong2 w0 = wr[0];
                wp[0] = w0.x; wp[1] = w0.y;
                if constexpr (PAIRS == 4) {
                    ulonglong2 w1 = wr[1];
                    wp[2] = w1.x; wp[3] = w1.y;
                }
            }
            #pragma unroll
            for (int p = 0; p < PAIRS; p++) {
                ffma2(acc2[p][0], wp[p], xd0);
                ffma2(acc2[p][1], wp[p], xd1);
                ffma2(acc2[p][2], wp[p], xd2);
                ffma2(acc2[p][3], wp[p], xd3);
            }
        }
        st = (st == 2) ? 0 : st + 1;
        stn = (stn == 2) ? 0 : stn + 1;
    }

    float acc[OPT][4];
    #pragma unroll
    for (int p = 0; p < PAIRS; p++)
        #pragma unroll
        for (int j = 0; j < 4; j++) {
            acc[2 * p][j]     = lo2(acc2[p][j]);
            acc[2 * p + 1][j] = hi2(acc2[p][j]);
        }
    const float INVS = rsqrtf(1.0f + 1e-5f);

    if constexpr (EPI == 3) {
        __shared__ float red[OT][17];
        #pragma unroll
        for (int i = 0; i < OPT; i++) {
            int o = oBase + to * OPT + i;
            float s = p0[o] * INVS, b = p1[o];
            float m = -FLT_MAX;
            #pragma unroll
            for (int j = 0; j < 4; j++)
                m = fmaxf(m, fmaxf(fmaf(acc[i][j], s, b), 0.0f));
            red[to * OPT + i][tn] = m;
        }
        __syncthreads();
        if (t < OT) {
            float m = red[t][0];
            #pragma unroll
            for (int q = 1; q < 16; q++) m = fmaxf(m, red[t][q]);
            int bb = g >> 8, mm = g & 255;   // g = b*256 + m
            out[((size_t)bb * 512 + oBase + t) * 256 + mm] = m;
        }
    } else {
        #pragma unroll
        for (int i = 0; i < OPT; i++) {
            int o = oBase + to * OPT + i;
            size_t ob = (size_t)g * outImgStride + (size_t)(chanOff + o) * outCpi
                      + colBase + (tn << 2);
            if constexpr (EPI == 0) {
                #pragma unroll
                for (int j = 0; j < 4; j++) out[ob + j] = acc[i][j];
            } else if constexpr (EPI == 1) {
                float s = p0[o] * INVS, b = p1[o];
                #pragma unroll
                for (int j = 0; j < 4; j++)
                    out[ob + j] = fmaxf(fmaf(acc[i][j], s, b), 0.0f);
            } else if constexpr (EPI == 2) {
                float bb = p0[o];
                #pragma unroll
                for (int j = 0; j < 4; j++) {
                    float v = acc[i][j] + bb;
                    float sg = 1.0f / (1.0f + expf(-v));
                    out[ob + j] = sg * aux[ob + j];
                }
            } else if constexpr (EPI == 4) {
                float sr = p0[o] * INVS, br = p1[o];
                float s1 = p2[o] * INVS, b1 = p3[o];
                #pragma unroll
                for (int j = 0; j < 4; j++) {
                    float r = fmaxf(fmaf(acc[i][j], sr, br), 0.0f);
                    out[ob + j] = fmaf(2.0f * r, s1, b1);
                }
            } else if constexpr (EPI == 5) {
                float bb = p0[o];
                #pragma unroll
                for (int j = 0; j < 4; j++)
                    out[ob + j] = fmaxf(acc[i][j] + bb, 0.0f);
            } else if constexpr (EPI == 6) {
                float bb = p0[o], s2 = p1[o] * INVS, b2 = p2[o];
                #pragma unroll
                for (int j = 0; j < 4; j++) {
                    float v = acc[i][j] + bb + aux[ob + j];
                    out[ob + j] = fmaf(v, s2, b2);
                }
            }
        }
    }
}

// ---------------------------------------------------------------------------
extern "C" void kernel_launch(void* const* d_in, const int* in_sizes, int n_in,
                              void* d_out, int out_size) {
    const float* xyz       = (const float*)d_in[0];
    const float* feats     = (const float*)d_in[1];
    const float* e1_w      = (const float*)d_in[2];
    const float* e1_g      = (const float*)d_in[3];
    const float* e1_b      = (const float*)d_in[4];
    const float* e2_w      = (const float*)d_in[5];
    const float* e2_g      = (const float*)d_in[6];
    const float* e2_b      = (const float*)d_in[7];
    const float* cal1_w    = (const float*)d_in[8];
    const float* cal1_g    = (const float*)d_in[9];
    const float* cal1_b    = (const float*)d_in[10];
    const float* cal2_w    = (const float*)d_in[11];
    const float* cal2_bias = (const float*)d_in[12];
    const float* exp1_w    = (const float*)d_in[13];
    const float* exp1_g    = (const float*)d_in[14];
    const float* exp1_b    = (const float*)d_in[15];
    const float* exp2_w    = (const float*)d_in[16];
    const float* exp2_g    = (const float*)d_in[17];
    const float* exp2_b    = (const float*)d_in[18];
    const float* red_w     = (const float*)d_in[19];
    const float* red_g     = (const float*)d_in[20];
    const float* red_b     = (const float*)d_in[21];
    const float* sc1_w     = (const float*)d_in[22];
    const float* sc1_b     = (const float*)d_in[23];
    const float* sc2_w     = (const float*)d_in[24];
    const float* sc2_b     = (const float*)d_in[25];
    const float* n1_g      = (const float*)d_in[26];
    const float* n1_b      = (const float*)d_in[27];
    const float* n2_g      = (const float*)d_in[28];
    const float* n2_b      = (const float*)d_in[29];

    float *dx, *dbig, *dcat, *dc, *dgt, *dx1, *dh, *dwt;
    cudaGetSymbolAddress((void**)&dx,   d_x_);
    cudaGetSymbolAddress((void**)&dbig, d_big_);
    cudaGetSymbolAddress((void**)&dcat, d_cat_);
    cudaGetSymbolAddress((void**)&dc,   d_c_);
    cudaGetSymbolAddress((void**)&dgt,  d_gt_);
    cudaGetSymbolAddress((void**)&dx1,  d_x1_);
    cudaGetSymbolAddress((void**)&dh,   d_h_);
    cudaGetSymbolAddress((void**)&dwt,  d_wt_);

    // K0 a/b: transpose weights (split so ncu launch #5 is a GEMM)
    prep_pack<<<(WP_EXP2 + 255) / 256, 256>>>(e1_w, e2_w, cal1_w, cal2_w, exp1_w,
                                              exp2_w, red_w, sc1_w, sc2_w, 0);
    prep_pack<<<(WP_TOT - WP_EXP2 + 255) / 256, 256>>>(e1_w, e2_w, cal1_w, cal2_w, exp1_w,
                                                       exp2_w, red_w, sc1_w, sc2_w, 1);
    // K1: input panel + knn
    knn_kernel<<<512, 64>>>(xyz, feats);

    // EdgeConv1: [U;T] = ws1(128x64) @ x  -> gather-max -> d_cat[0:64)
    gemm_k<0, 128><<<dim3(512, 1, 1), 256>>>(dx, 4096, 64, dwt + WP_WS1, 64, 128,
                                             dbig, 8192, 64, 0,
                                             nullptr, nullptr, nullptr, nullptr, nullptr);
    gather_kernel<<<512, 256>>>(dbig, e1_g, e1_b, 64, 0);

    // EdgeConv2 (ncu launch #5): [U;T] = ws2(256x64) @ d_cat[0:64)
    gemm_k<0, 128><<<dim3(512, 1, 2), 256>>>(dcat, 12288, 64, dwt + WP_WS2, 64, 256,
                                             dbig, 16384, 64, 0,
                                             nullptr, nullptr, nullptr, nullptr, nullptr);
    gather_kernel<<<512, 256>>>(dbig, e2_g, e2_b, 128, 64);

    // calib: c = relu(bn(cal1@x)); x = sigmoid(cal2@c + bias) * x  (gate in-place)
    gemm_k<1, 64><<<dim3(512, 1, 1), 256>>>(dcat, 12288, 64, dwt + WP_CAL1, 192, 64,
                                            dc, 4096, 64, 0,
                                            cal1_g, cal1_b, nullptr, nullptr, nullptr);
    gemm_k<2, 64><<<dim3(512, 1, 3), 256>>>(dc, 4096, 64, dwt + WP_CAL2, 64, 192,
                                            dcat, 12288, 64, 0,
                                            cal2_bias, nullptr, nullptr, nullptr, dcat);

    // exp1: relu(bn(exp1@x))
    gemm_k<1, 128><<<dim3(512, 1, 2), 256>>>(dcat, 12288, 64, dwt + WP_EXP1, 192, 256,
                                             dbig, 16384, 64, 0,
                                             exp1_g, exp1_b, nullptr, nullptr, nullptr);
    // exp2 + max over 64 points, write transposed pooled [b][512][256]
    gemm_k<3, 128><<<dim3(512, 1, 4), 256>>>(dbig, 16384, 64, dwt + WP_EXP2, 256, 512,
                                             dgt, 0, 0, 0,
                                             exp2_g, exp2_b, nullptr, nullptr, nullptr);

    // red: x1 = bn1( 2 * relu(bn(red@pooled)) )
    gemm_k<4, 128><<<dim3(2, 4, 2), 256>>>(dgt, 131072, 256, dwt + WP_RED, 512, 256,
                                           dx1, 65536, 256, 0,
                                           red_g, red_b, n1_g, n1_b, nullptr);
    // sc1: h = relu(sc1@x1 + b)
    gemm_k<5, 128><<<dim3(2, 4, 2), 256>>>(dx1, 65536, 256, dwt + WP_SC1, 256, 256,
                                           dh, 65536, 256, 0,
                                           sc1_b, nullptr, nullptr, nullptr, nullptr);
    // sc2 + residual + bn2 -> final output (B, 256, 256)
    gemm_k<6, 128><<<dim3(2, 4, 2), 256>>>(dh, 65536, 256, dwt + WP_SC2, 256, 256,
                                           (float*)d_out, 65536, 256, 0,
                                           sc2_b, n2_g, n2_b, nullptr, dx1);
}

// round 11
// speedup vs baseline: 2.7082x; 1.0966x over previous
#include <cuda_runtime.h>
#include <cstdint>
#include <cfloat>
#include <math.h>

// ---------------------------------------------------------------------------
// Problem constants
//   B=2, M=256 -> 512 groups, 64 points/group, KNN=16, CIN=64 (3 xyz + 61 feat)
//   MLPS=[64,128], SUMM=192, CALIB=64, EXP=[256,512], OUT=256
// ---------------------------------------------------------------------------

// Scratch (static device arrays; no runtime allocation)
__device__ float d_x_[512 * 64 * 64];      // input panel  [g][c(64)][n(64)]
__device__ int   d_idx_[512 * 64 * 16];    // knn indices  [g][n][k]
__device__ float d_big_[512 * 256 * 64];   // exp1 out
__device__ float d_cat_[512 * 192 * 64];   // concat features [g][c(192)][n]
__device__ float d_c_[512 * 64 * 64];      // cal1 out
__device__ float d_gt_[2 * 512 * 256];     // pooled vector, [b][c(512)][m(256)]
__device__ float d_x1_[2 * 256 * 256];     // after red+bn1
__device__ float d_h_[2 * 256 * 256];      // sc1 out

// All weights, transposed to [c][o] (plain float — o-pairs are natural f32x2).
//   ws1   @0       64c x 128o  ([W1(64) ; W2-W1(64)])
//   ws2   @8192    64c x 256o  per-block interleave: o'=half*128+r,
//                              r<64 -> W1 row half*64+r ; r>=64 -> (W2-W1) row half*64+(r-64)
//   cal1  @24576  192c x  64o
//   cal2  @36864   64c x 192o
//   exp1  @49152  192c x 256o
//   exp2  @98304  256c x 512o
//   red   @229376 512c x 256o
//   sc1   @360448 256c x 256o
//   sc2   @425984 256c x 256o
#define WP_WS1  0
#define WP_WS2  8192
#define WP_CAL1 24576
#define WP_CAL2 36864
#define WP_EXP1 49152
#define WP_EXP2 98304
#define WP_RED  229376
#define WP_SC1  360448
#define WP_SC2  425984
#define WP_TOT  491520
__device__ float d_wt_[WP_TOT];

// ---------------------------------------------------------------------------
// f32x2 packed-FMA + cp.async helpers
// ---------------------------------------------------------------------------
__device__ __forceinline__ unsigned long long pack2(float v) {
    unsigned long long r;
    asm("mov.b64 %0, {%1, %1};" : "=l"(r) : "r"(__float_as_uint(v)));
    return r;
}
__device__ __forceinline__ void ffma2(unsigned long long& d,
                                      unsigned long long a, unsigned long long b) {
    asm("fma.rn.f32x2 %0, %1, %2, %0;" : "+l"(d) : "l"(a), "l"(b));
}
__device__ __forceinline__ float lo2(unsigned long long v) { return __uint_as_float((unsigned)v); }
__device__ __forceinline__ float hi2(unsigned long long v) { return __uint_as_float((unsigned)(v >> 32)); }

__device__ __forceinline__ void cp16(unsigned int dst, const void* src) {
    asm volatile("cp.async.cg.shared.global [%0], [%1], 16;" :: "r"(dst), "l"(src));
}
__device__ __forceinline__ void cp_commit() { asm volatile("cp.async.commit_group;"); }
template<int N> __device__ __forceinline__ void cp_wait() {
    asm volatile("cp.async.wait_group %0;" :: "n"(N));
}

// ---------------------------------------------------------------------------
// K0 (x2 launches): transpose ALL weights into d_wt_ ([c][o], plain float).
// ---------------------------------------------------------------------------
__global__ void prep_pack(const float* __restrict__ e1w, const float* __restrict__ e2w,
                          const float* __restrict__ cal1w, const float* __restrict__ cal2w,
                          const float* __restrict__ exp1w, const float* __restrict__ exp2w,
                          const float* __restrict__ redw, const float* __restrict__ sc1w,
                          const float* __restrict__ sc2w, int part) {
    int i = blockIdx.x * blockDim.x + threadIdx.x + (part ? WP_EXP2 : 0);
    if (part == 0) {
        if (i >= WP_EXP2) return;
    } else {
        if (i >= WP_TOT) return;
    }
    float v;
    if (i < WP_WS2) {                 // ws1: O=128, C=64
        int l = i - WP_WS1, c = l >> 7, o = l & 127;
        v = (o < 64) ? e1w[o * 128 + c]
                     : e1w[(o - 64) * 128 + 64 + c] - e1w[(o - 64) * 128 + c];
    } else if (i < WP_CAL1) {         // ws2: O=256 (per-block [U;T] interleave)
        int l = i - WP_WS2, c = l >> 8, op = l & 255;
        int half = op >> 7, r = op & 127;
        int row = half * 64 + (r & 63);
        v = (r < 64) ? e2w[row * 128 + c]
                     : e2w[row * 128 + 64 + c] - e2w[row * 128 + c];
    } else if (i < WP_CAL2) {         // cal1: O=64, C=192
        int l = i - WP_CAL1, c = l >> 6, o = l & 63;
        v = cal1w[o * 192 + c];
    } else if (i < WP_EXP1) {         // cal2: O=192, C=64
        int l = i - WP_CAL2, c = l / 192, o = l % 192;
        v = cal2w[o * 64 + c];
    } else if (i < WP_EXP2) {         // exp1: O=256, C=192
        int l = i - WP_EXP1, c = l >> 8, o = l & 255;
        v = exp1w[o * 192 + c];
    } else if (i < WP_RED) {          // exp2: O=512, C=256
        int l = i - WP_EXP2, c = l >> 9, o = l & 511;
        v = exp2w[o * 256 + c];
    } else if (i < WP_SC1) {          // red: O=256, C=512
        int l = i - WP_RED, c = l >> 8, o = l & 255;
        v = redw[o * 512 + c];
    } else if (i < WP_SC2) {          // sc1: O=256, C=256
        int l = i - WP_SC1, c = l >> 8, o = l & 255;
        v = sc1w[o * 256 + c];
    } else {                          // sc2: O=256, C=256
        int l = i - WP_SC2, c = l >> 8, o = l & 255;
        v = sc2w[o * 256 + c];
    }
    d_wt_[i] = v;
}

// ---------------------------------------------------------------------------
// K1: build input panel d_x (xyz+feats transposed) + 16-NN per point.
// ---------------------------------------------------------------------------
__global__ void knn_kernel(const float* __restrict__ xyz, const float* __restrict__ feats) {
    int g = blockIdx.x, t = threadIdx.x;
    __shared__ float px[64], py[64], pz[64], xx[64];
    __shared__ float sbuf[64 * 65];   // feat staging (3904) / padded pd rows (64x65)

    int b3 = (g * 64 + t) * 3;
    float ax = xyz[b3 + 0], ay = xyz[b3 + 1], az = xyz[b3 + 2];
    px[t] = ax; py[t] = ay; pz[t] = az;
    xx[t] = ax * ax + ay * ay + az * az;

    float* xg = d_x_ + (size_t)g * 4096;
    xg[0 * 64 + t] = ax; xg[1 * 64 + t] = ay; xg[2 * 64 + t] = az;

    const float* fg = feats + (size_t)g * 64 * 61;
    for (int i = 0; i < 61; i++) sbuf[i * 64 + t] = fg[i * 64 + t];
    __syncthreads();
    for (int c = 0; c < 61; c++) xg[(3 + c) * 64 + t] = sbuf[t * 61 + c];
    __syncthreads();

    float* row = &sbuf[t * 65];
    float xn = xx[t];
    for (int m = 0; m < 64; m++)
        row[m] = 2.0f * (ax * px[m] + ay * py[m] + az * pz[m]) - xn - xx[m];

    // top-16 by selection (only the SET matters; max-over-k is order-invariant)
    int* ig = d_idx_ + (g * 64 + t) * 16;
    for (int k = 0; k < 16; k++) {
        float best = -FLT_MAX; int bi = 0;
        for (int m = 0; m < 64; m++) {
            float v = row[m];
            if (v > best) { best = v; bi = m; }
        }
        ig[k] = bi;
        row[bi] = -FLT_MAX;
    }
}

// ---------------------------------------------------------------------------
// Fused GEMM, o-paired FFMA2:  out(OT o x 64col) = epi( W @ X )
// W pre-transposed [c][wO] plain float: consecutive o's ARE the f32x2 pair.
// 3-stage cp.async pipeline, one sync per 16-channel chunk.
// Epilogues: 0 raw | 1 relu(bn) | 2 sigmoid-gate | 3 relu(bn)+max-over-col
//            4 red: relu(bn)*2->bn1 | 5 bias+relu | 6 final bn2(x1+acc+b)
//            7 EdgeConv fused gather-max (OT=128: rows 0..63=U, 64..127=T)
// ---------------------------------------------------------------------------
template<int EPI, int OT>
__global__ void __launch_bounds__(256)
gemm_k(const float* __restrict__ X, int imgStride, int cpi,
       const float* __restrict__ Wt, int CIN, int wO,
       float* out, int outImgStride, int outCpi, int chanOff,
       const float* p0, const float* p1, const float* p2, const float* p3,
       const float* aux) {
    constexpr int OPT = OT / 16;       // outputs per thread (8 or 4)
    constexpr int PAIRS = OPT / 2;     // f32x2 pairs per thread (4 or 2)
    constexpr int PIPE_F = 3 * 16 * 64 + 3 * 16 * OT;
    constexpr int EPI7_F = (EPI == 7) ? (4096 + 4096 + 64 * 17) : 0;
    constexpr int SM_F = PIPE_F > EPI7_F ? PIPE_F : EPI7_F;
    __shared__ __align__(16) float smbuf[SM_F];
    float* XsP = smbuf;                 // [(st*16+c)*64 + col]
    float* WsP = smbuf + 3 * 16 * 64;   // [(st*16+c)*OT + o]

    const int g = blockIdx.x;
    const int colBase = blockIdx.y << 6;
    const int oBase = blockIdx.z * OT;
    const int t = threadIdx.x;
    const int tn = t & 15, to = t >> 4;

    const float* Xg = X + (size_t)g * imgStride + colBase;

    // staging roles
    const int cr = t >> 4;             // chunk row 0..15
    const int xc = (t & 15) << 2;      // X col (float)
    const unsigned int xs_s = (unsigned int)__cvta_generic_to_shared(XsP);
    const unsigned int ws_s = (unsigned int)__cvta_generic_to_shared(WsP);
    const int nch = CIN >> 4;

    unsigned long long acc2[PAIRS][4];
    #pragma unroll
    for (int p = 0; p < PAIRS; p++)
        #pragma unroll
        for (int j = 0; j < 4; j++) acc2[p][j] = 0ull;

    auto prefetch = [&](int cb, int st) {
        if (cb < nch) {
            const int c0 = cb << 4;
            cp16(xs_s + (unsigned int)(st * 1024 + cr * 64 + xc) * 4,
                 Xg + (size_t)(c0 + cr) * cpi + xc);
            const float* wrow = Wt + (size_t)(c0 + cr) * wO + oBase;
            if constexpr (OT == 128) {
                const int wc = (t & 15) << 3;
                cp16(ws_s + (unsigned int)(st * 16 * OT + cr * OT + wc) * 4, wrow + wc);
                cp16(ws_s + (unsigned int)(st * 16 * OT + cr * OT + wc + 4) * 4, wrow + wc + 4);
            } else {
                const int wc = (t & 15) << 2;
                cp16(ws_s + (unsigned int)(st * 16 * OT + cr * OT + wc) * 4, wrow + wc);
            }
        }
        cp_commit();
    };

    prefetch(0, 0);
    prefetch(1, 1);

    int st = 0, stn = 2;
    for (int cb = 0; cb < nch; cb++) {
        cp_wait<1>();
        __syncthreads();
        prefetch(cb + 2, stn);
        #pragma unroll
        for (int c = 0; c < 16; c++) {
            float4 xv = *reinterpret_cast<const float4*>(&XsP[(st * 16 + c) * 64 + (tn << 2)]);
            unsigned long long xd0 = pack2(xv.x), xd1 = pack2(xv.y);
            unsigned long long xd2 = pack2(xv.z), xd3 = pack2(xv.w);
            const ulonglong2* wr =
                reinterpret_cast<const ulonglong2*>(&WsP[(st * 16 + c) * OT + to * OPT]);
            unsigned long long wp[PAIRS];
            {
                ulonglong2 w0 = wr[0];
                wp[0] = w0.x; wp[1] = w0.y;
                if constexpr (PAIRS == 4) {
                    ulonglong2 w1 = wr[1];
                    wp[2] = w1.x; wp[3] = w1.y;
                }
            }
            #pragma unroll
            for (int p = 0; p < PAIRS; p++) {
                ffma2(acc2[p][0], wp[p], xd0);
                ffma2(acc2[p][1], wp[p], xd1);
                ffma2(acc2[p][2], wp[p], xd2);
                ffma2(acc2[p][3], wp[p], xd3);
            }
        }
        st = (st == 2) ? 0 : st + 1;
        stn = (stn == 2) ? 0 : stn + 1;
    }

    float acc[OPT][4];
    #pragma unroll
    for (int p = 0; p < PAIRS; p++)
        #pragma unroll
        for (int j = 0; j < 4; j++) {
            acc[2 * p][j]     = lo2(acc2[p][j]);
            acc[2 * p + 1][j] = hi2(acc2[p][j]);
        }
    const float INVS = rsqrtf(1.0f + 1e-5f);

    if constexpr (EPI == 7) {
        // Fused EdgeConv gather-max. Rows 0..63 = U, 64..127 = T (local o).
        float* Us = smbuf;            // [o*64 + n]
        float* Ts = smbuf + 4096;     // [o*64 + n]
        int*   sidx = (int*)(smbuf + 8192);   // [n*17 + k]
        __syncthreads();   // all warps done reading pipeline smem
        #pragma unroll
        for (int i = 0; i < OPT; i++) {
            int r = to * OPT + i;          // 0..127
            float* dst = (r < 64) ? &Us[r * 64] : &Ts[(r - 64) * 64];
            #pragma unroll
            for (int j = 0; j < 4; j++) dst[(tn << 2) + j] = acc[i][j];
        }
        const int* idg = d_idx_ + g * 1024;
        for (int i = t; i < 1024; i += 256)
            sidx[(i >> 4) * 17 + (i & 15)] = idg[i];
        __syncthreads();

        const int bnoff = blockIdx.z << 6;
        float* outg = out + (size_t)g * outImgStride + (size_t)(chanOff + bnoff) * outCpi;
        for (int item = t; item < 4096; item += 256) {
            int o = item >> 6, n = item & 63;
            float T = Ts[o * 64 + n];
            float s = p0[bnoff + o] * INVS, b = p1[bnoff + o];
            const float* Uo = &Us[o * 64];
            const int*   ni = &sidx[n * 17];
            float m = -FLT_MAX;
            #pragma unroll
            for (int k = 0; k < 16; k++) {
                float v = fmaf(Uo[ni[k]] + T, s, b);
                m = fmaxf(m, fmaxf(v, 0.0f));
            }
            outg[o * (size_t)outCpi + n] = m;
        }
    } else if constexpr (EPI == 3) {
        float* red = smbuf;   // [r*17 + q]
        __syncthreads();      // all warps done reading pipeline smem
        #pragma unroll
        for (int i = 0; i < OPT; i++) {
            int o = oBase + to * OPT + i;
            float s = p0[o] * INVS, b = p1[o];
            float m = -FLT_MAX;
            #pragma unroll
            for (int j = 0; j < 4; j++)
                m = fmaxf(m, fmaxf(fmaf(acc[i][j], s, b), 0.0f));
            red[(to * OPT + i) * 17 + tn] = m;
        }
        __syncthreads();
        if (t < OT) {
            float m = red[t * 17];
            #pragma unroll
            for (int q = 1; q < 16; q++) m = fmaxf(m, red[t * 17 + q]);
            int bb = g >> 8, mm = g & 255;   // g = b*256 + m
            out[((size_t)bb * 512 + oBase + t) * 256 + mm] = m;
        }
    } else {
        #pragma unroll
        for (int i = 0; i < OPT; i++) {
            int o = oBase + to * OPT + i;
            size_t ob = (size_t)g * outImgStride + (size_t)(chanOff + o) * outCpi
                      + colBase + (tn << 2);
            if constexpr (EPI == 0) {
                #pragma unroll
                for (int j = 0; j < 4; j++) out[ob + j] = acc[i][j];
            } else if constexpr (EPI == 1) {
                float s = p0[o] * INVS, b = p1[o];
                #pragma unroll
                for (int j = 0; j < 4; j++)
                    out[ob + j] = fmaxf(fmaf(acc[i][j], s, b), 0.0f);
            } else if constexpr (EPI == 2) {
                float bb = p0[o];
                #pragma unroll
                for (int j = 0; j < 4; j++) {
                    float v = acc[i][j] + bb;
                    float sg = 1.0f / (1.0f + expf(-v));
                    out[ob + j] = sg * aux[ob + j];
                }
            } else if constexpr (EPI == 4) {
                float sr = p0[o] * INVS, br = p1[o];
                float s1 = p2[o] * INVS, b1 = p3[o];
                #pragma unroll
                for (int j = 0; j < 4; j++) {
                    float r = fmaxf(fmaf(acc[i][j], sr, br), 0.0f);
                    out[ob + j] = fmaf(2.0f * r, s1, b1);
                }
            } else if constexpr (EPI == 5) {
                float bb = p0[o];
                #pragma unroll
                for (int j = 0; j < 4; j++)
                    out[ob + j] = fmaxf(acc[i][j] + bb, 0.0f);
            } else if constexpr (EPI == 6) {
                float bb = p0[o], s2 = p1[o] * INVS, b2 = p2[o];
                #pragma unroll
                for (int j = 0; j < 4; j++) {
                    float v = acc[i][j] + bb + aux[ob + j];
                    out[ob + j] = fmaf(v, s2, b2);
                }
            }
        }
    }
}

// ---------------------------------------------------------------------------
extern "C" void kernel_launch(void* const* d_in, const int* in_sizes, int n_in,
                              void* d_out, int out_size) {
    const float* xyz       = (const float*)d_in[0];
    const float* feats     = (const float*)d_in[1];
    const float* e1_w      = (const float*)d_in[2];
    const float* e1_g      = (const float*)d_in[3];
    const float* e1_b      = (const float*)d_in[4];
    const float* e2_w      = (const float*)d_in[5];
    const float* e2_g      = (const float*)d_in[6];
    const float* e2_b      = (const float*)d_in[7];
    const float* cal1_w    = (const float*)d_in[8];
    const float* cal1_g    = (const float*)d_in[9];
    const float* cal1_b    = (const float*)d_in[10];
    const float* cal2_w    = (const float*)d_in[11];
    const float* cal2_bias = (const float*)d_in[12];
    const float* exp1_w    = (const float*)d_in[13];
    const float* exp1_g    = (const float*)d_in[14];
    const float* exp1_b    = (const float*)d_in[15];
    const float* exp2_w    = (const float*)d_in[16];
    const float* exp2_g    = (const float*)d_in[17];
    const float* exp2_b    = (const float*)d_in[18];
    const float* red_w     = (const float*)d_in[19];
    const float* red_g     = (const float*)d_in[20];
    const float* red_b     = (const float*)d_in[21];
    const float* sc1_w     = (const float*)d_in[22];
    const float* sc1_b     = (const float*)d_in[23];
    const float* sc2_w     = (const float*)d_in[24];
    const float* sc2_b     = (const float*)d_in[25];
    const float* n1_g      = (const float*)d_in[26];
    const float* n1_b      = (const float*)d_in[27];
    const float* n2_g      = (const float*)d_in[28];
    const float* n2_b      = (const float*)d_in[29];

    float *dx, *dbig, *dcat, *dc, *dgt, *dx1, *dh, *dwt;
    cudaGetSymbolAddress((void**)&dx,   d_x_);
    cudaGetSymbolAddress((void**)&dbig, d_big_);
    cudaGetSymbolAddress((void**)&dcat, d_cat_);
    cudaGetSymbolAddress((void**)&dc,   d_c_);
    cudaGetSymbolAddress((void**)&dgt,  d_gt_);
    cudaGetSymbolAddress((void**)&dx1,  d_x1_);
    cudaGetSymbolAddress((void**)&dh,   d_h_);
    cudaGetSymbolAddress((void**)&dwt,  d_wt_);

    // K0 a/b: transpose weights
    prep_pack<<<(WP_EXP2 + 255) / 256, 256>>>(e1_w, e2_w, cal1_w, cal2_w, exp1_w,
                                              exp2_w, red_w, sc1_w, sc2_w, 0);
    prep_pack<<<(WP_TOT - WP_EXP2 + 255) / 256, 256>>>(e1_w, e2_w, cal1_w, cal2_w, exp1_w,
                                                       exp2_w, red_w, sc1_w, sc2_w, 1);
    // K1: input panel + knn
    knn_kernel<<<512, 64>>>(xyz, feats);

    // EdgeConv1 fused (GEMM + gather-max) -> d_cat[0:64)
    gemm_k<7, 128><<<dim3(512, 1, 1), 256>>>(dx, 4096, 64, dwt + WP_WS1, 64, 128,
                                             dcat, 12288, 64, 0,
                                             e1_g, e1_b, nullptr, nullptr, nullptr);
    // EdgeConv2 fused -> d_cat[64:192)   (z: two [U;T] halves)
    gemm_k<7, 128><<<dim3(512, 1, 2), 256>>>(dcat, 12288, 64, dwt + WP_WS2, 64, 256,
                                             dcat, 12288, 64, 64,
                                             e2_g, e2_b, nullptr, nullptr, nullptr);

    // calib: c = relu(bn(cal1@x)); x = sigmoid(cal2@c + bias) * x  (gate in-place)
    gemm_k<1, 64><<<dim3(512, 1, 1), 256>>>(dcat, 12288, 64, dwt + WP_CAL1, 192, 64,
                                            dc, 4096, 64, 0,
                                            cal1_g, cal1_b, nullptr, nullptr, nullptr);
    gemm_k<2, 64><<<dim3(512, 1, 3), 256>>>(dc, 4096, 64, dwt + WP_CAL2, 64, 192,
                                            dcat, 12288, 64, 0,
                                            cal2_bias, nullptr, nullptr, nullptr, dcat);

    // exp1: relu(bn(exp1@x))
    gemm_k<1, 128><<<dim3(512, 1, 2), 256>>>(dcat, 12288, 64, dwt + WP_EXP1, 192, 256,
                                             dbig, 16384, 64, 0,
                                             exp1_g, exp1_b, nullptr, nullptr, nullptr);
    // exp2 + max over 64 points, write transposed pooled [b][512][256]
    gemm_k<3, 128><<<dim3(512, 1, 4), 256>>>(dbig, 16384, 64, dwt + WP_EXP2, 256, 512,
                                             dgt, 0, 0, 0,
                                             exp2_g, exp2_b, nullptr, nullptr, nullptr);

    // red: x1 = bn1( 2 * relu(bn(red@pooled)) )   (OT=64 -> 32 blocks)
    gemm_k<4, 64><<<dim3(2, 4, 4), 256>>>(dgt, 131072, 256, dwt + WP_RED, 512, 256,
                                          dx1, 65536, 256, 0,
                                          red_g, red_b, n1_g, n1_b, nullptr);
    // sc1: h = relu(sc1@x1 + b)
    gemm_k<5, 64><<<dim3(2, 4, 4), 256>>>(dx1, 65536, 256, dwt + WP_SC1, 256, 256,
                                          dh, 65536, 256, 0,
                                          sc1_b, nullptr, nullptr, nullptr, nullptr);
    // sc2 + residual + bn2 -> final output (B, 256, 256)
    gemm_k<6, 64><<<dim3(2, 4, 4), 256>>>(dh, 65536, 256, dwt + WP_SC2, 256, 256,
                                          (float*)d_out, 65536, 256, 0,
                                          sc2_b, n2_g, n2_b, nullptr, dx1);
}